// round 1
// baseline (speedup 1.0000x reference)
#include <cuda_runtime.h>
#include <math.h>

#define Bn   16
#define CIN  512
#define Lr   1024
#define COUT 1024
#define KW   5
#define DW   512
#define HW   196
#define HALF 512

// ---- scratch (device globals; no allocation allowed) ----
__device__ float g_wn[COUT * CIN * KW];        // normalized conv weights
__device__ float g_y[(size_t)Bn * COUT * Lr];  // conv output (pre-GLU)
__device__ float g_h[(size_t)Bn * HALF * Lr];  // GLU output / identity_attn
__device__ float g_q[(size_t)Bn * Lr * DW];    // fc1 output + word_embed
__device__ float g_score[(size_t)Bn * Lr * HW];
__device__ float g_ctx[(size_t)Bn * Lr * DW];

// ================= weight norm =================
__global__ void wnorm_kernel(const float* __restrict__ v, const float* __restrict__ g) {
    int co = blockIdx.x;
    const float* vp = v + (size_t)co * (CIN * KW);
    float s = 0.f;
    for (int i = threadIdx.x; i < CIN * KW; i += blockDim.x) {
        float t = vp[i];
        s += t * t;
    }
    __shared__ float red[256];
    red[threadIdx.x] = s;
    __syncthreads();
    for (int o = 128; o > 0; o >>= 1) {
        if (threadIdx.x < o) red[threadIdx.x] += red[threadIdx.x + o];
        __syncthreads();
    }
    float scale = g[co] * rsqrtf(red[0]);
    for (int i = threadIdx.x; i < CIN * KW; i += blockDim.x)
        g_wn[(size_t)co * (CIN * KW) + i] = vp[i] * scale;
}

// ================= causal conv (tile 128co x 128l, 8x8 reg tile) =================
__global__ void __launch_bounds__(256) conv_kernel(const float* __restrict__ x,
                                                   const float* __restrict__ bias) {
    __shared__ float Ws[40][132];   // [ci_local*5+t][co_row]
    __shared__ float Xs[8][136];    // [ci_local][l0-4+j]
    int l0 = blockIdx.x * 128;
    int co0 = blockIdx.y * 128;
    int b = blockIdx.z;
    int tid = threadIdx.x;
    int tx = tid & 15, ty = tid >> 4;
    const float* xb = x + (size_t)b * CIN * Lr;

    float acc[8][8];
#pragma unroll
    for (int i = 0; i < 8; ++i)
#pragma unroll
        for (int j = 0; j < 8; ++j) acc[i][j] = 0.f;

    for (int chunk = 0; chunk < 64; ++chunk) {
        int ci0 = chunk * 8;
        for (int idx = tid; idx < 40 * 128; idx += 256) {
            int kk = idx % 40, row = idx / 40;
            Ws[kk][row] = g_wn[(size_t)(co0 + row) * (CIN * KW) + ci0 * KW + kk];
        }
        for (int idx = tid; idx < 8 * 132; idx += 256) {
            int j = idx % 132, ci = idx / 132;
            int xp = l0 - 4 + j;
            Xs[ci][j] = (xp >= 0) ? xb[(size_t)(ci0 + ci) * Lr + xp] : 0.f;
        }
        __syncthreads();
        for (int ci = 0; ci < 8; ++ci) {
#pragma unroll
            for (int t = 0; t < 5; ++t) {
                float wv[8], xv[8];
#pragma unroll
                for (int j = 0; j < 8; ++j) wv[j] = Ws[ci * 5 + t][ty + 16 * j];
#pragma unroll
                for (int j = 0; j < 8; ++j) xv[j] = Xs[ci][tx + 16 * j + t];
#pragma unroll
                for (int jr = 0; jr < 8; ++jr)
#pragma unroll
                    for (int jc = 0; jc < 8; ++jc) acc[jr][jc] += wv[jr] * xv[jc];
            }
        }
        __syncthreads();
    }
#pragma unroll
    for (int jr = 0; jr < 8; ++jr) {
        int co = co0 + ty + 16 * jr;
        float bb = bias[co];
#pragma unroll
        for (int jc = 0; jc < 8; ++jc) {
            int l = l0 + tx + 16 * jc;
            g_y[((size_t)b * COUT + co) * Lr + l] = acc[jr][jc] + bb;
        }
    }
}

// ================= GLU =================
__global__ void glu_kernel() {
    size_t i = (size_t)blockIdx.x * 256 + threadIdx.x;  // over Bn*HALF*Lr
    int l = (int)(i & 1023);
    size_t rest = i >> 10;
    int c = (int)(rest & 511);
    int b = (int)(rest >> 9);
    float a = g_y[((size_t)b * COUT + c) * Lr + l];
    float bb = g_y[((size_t)b * COUT + c + HALF) * Lr + l];
    g_h[i] = a * (1.f / (1.f + expf(-bb)));
}

// ================= fc1: q = h^T W1^T + b1 + we =================
__global__ void __launch_bounds__(256) fc1_kernel(const float* __restrict__ w,
                                                  const float* __restrict__ bias,
                                                  const float* __restrict__ we) {
    __shared__ float As[16][132], Bs[16][132];
    int a0 = blockIdx.x * 128;
    int m0 = blockIdx.y * 128;
    int b = m0 >> 10, l0 = m0 & 1023;
    int tid = threadIdx.x, tx = tid & 15, ty = tid >> 4;
    float acc[8][8];
#pragma unroll
    for (int i = 0; i < 8; ++i)
#pragma unroll
        for (int j = 0; j < 8; ++j) acc[i][j] = 0.f;

    for (int k0 = 0; k0 < DW; k0 += 16) {
        for (int idx = tid; idx < 2048; idx += 256) {
            int mm = idx & 127, kk = idx >> 7;
            As[kk][mm] = g_h[((size_t)b * HALF + k0 + kk) * Lr + l0 + mm];
        }
        for (int idx = tid; idx < 2048; idx += 256) {
            int kk = idx & 15, nn = idx >> 4;
            Bs[kk][nn] = w[(size_t)(a0 + nn) * DW + k0 + kk];
        }
        __syncthreads();
#pragma unroll
        for (int kk = 0; kk < 16; ++kk) {
            float av[8], bv[8];
#pragma unroll
            for (int j = 0; j < 8; ++j) av[j] = As[kk][ty + 16 * j];
#pragma unroll
            for (int j = 0; j < 8; ++j) bv[j] = Bs[kk][tx + 16 * j];
#pragma unroll
            for (int jr = 0; jr < 8; ++jr)
#pragma unroll
                for (int jc = 0; jc < 8; ++jc) acc[jr][jc] += av[jr] * bv[jc];
        }
        __syncthreads();
    }
#pragma unroll
    for (int jr = 0; jr < 8; ++jr) {
        int m = m0 + ty + 16 * jr;
#pragma unroll
        for (int jc = 0; jc < 8; ++jc) {
            int a = a0 + tx + 16 * jc;
            g_q[(size_t)m * DW + a] = acc[jr][jc] + bias[a] + we[(size_t)m * DW + a];
        }
    }
}

// ================= score = q @ feat =================
__global__ void __launch_bounds__(256) score_kernel(const float* __restrict__ feat) {
    __shared__ float As[16][132], Bs[16][132];
    int p0 = blockIdx.x * 128;
    int m0 = blockIdx.y * 128;
    int b = m0 >> 10;
    int tid = threadIdx.x, tx = tid & 15, ty = tid >> 4;
    float acc[8][8];
#pragma unroll
    for (int i = 0; i < 8; ++i)
#pragma unroll
        for (int j = 0; j < 8; ++j) acc[i][j] = 0.f;

    for (int k0 = 0; k0 < DW; k0 += 16) {
        for (int idx = tid; idx < 2048; idx += 256) {
            int kk = idx & 15, mm = idx >> 4;
            As[kk][mm] = g_q[(size_t)(m0 + mm) * DW + k0 + kk];
        }
        for (int idx = tid; idx < 2048; idx += 256) {
            int nn = idx & 127, kk = idx >> 7;
            int p = p0 + nn;
            Bs[kk][nn] = (p < HW) ? feat[((size_t)b * DW + k0 + kk) * HW + p] : 0.f;
        }
        __syncthreads();
#pragma unroll
        for (int kk = 0; kk < 16; ++kk) {
            float av[8], bv[8];
#pragma unroll
            for (int j = 0; j < 8; ++j) av[j] = As[kk][ty + 16 * j];
#pragma unroll
            for (int j = 0; j < 8; ++j) bv[j] = Bs[kk][tx + 16 * j];
#pragma unroll
            for (int jr = 0; jr < 8; ++jr)
#pragma unroll
                for (int jc = 0; jc < 8; ++jc) acc[jr][jc] += av[jr] * bv[jc];
        }
        __syncthreads();
    }
#pragma unroll
    for (int jr = 0; jr < 8; ++jr) {
        int m = m0 + ty + 16 * jr;
#pragma unroll
        for (int jc = 0; jc < 8; ++jc) {
            int p = p0 + tx + 16 * jc;
            if (p < HW) g_score[(size_t)m * HW + p] = acc[jr][jc];
        }
    }
}

// ================= softmax over 196 (one warp per row) =================
__global__ void softmax_kernel(float* __restrict__ attn) {
    int warp = (blockIdx.x * blockDim.x + threadIdx.x) >> 5;
    int lane = threadIdx.x & 31;
    if (warp >= Bn * Lr) return;
    const float* sp = g_score + (size_t)warp * HW;
    float v[7];
    float mx = -1e30f;
#pragma unroll
    for (int i = 0; i < 7; ++i) {
        int p = lane + 32 * i;
        v[i] = (p < HW) ? sp[p] : -1e30f;
        mx = fmaxf(mx, v[i]);
    }
#pragma unroll
    for (int o = 16; o > 0; o >>= 1) mx = fmaxf(mx, __shfl_xor_sync(0xffffffffu, mx, o));
    float sum = 0.f;
#pragma unroll
    for (int i = 0; i < 7; ++i) {
        int p = lane + 32 * i;
        v[i] = (p < HW) ? expf(v[i] - mx) : 0.f;
        sum += v[i];
    }
#pragma unroll
    for (int o = 16; o > 0; o >>= 1) sum += __shfl_xor_sync(0xffffffffu, sum, o);
    float inv = 1.f / sum;
#pragma unroll
    for (int i = 0; i < 7; ++i) {
        int p = lane + 32 * i;
        if (p < HW) attn[(size_t)warp * HW + p] = v[i] * inv;
    }
}

// ================= ctx = attn @ feat^T =================
__global__ void __launch_bounds__(256) ctx_kernel(const float* __restrict__ attn,
                                                  const float* __restrict__ feat) {
    __shared__ float As[16][132], Bs[16][132];
    int a0 = blockIdx.x * 128;
    int m0 = blockIdx.y * 128;
    int b = m0 >> 10;
    int tid = threadIdx.x, tx = tid & 15, ty = tid >> 4;
    float acc[8][8];
#pragma unroll
    for (int i = 0; i < 8; ++i)
#pragma unroll
        for (int j = 0; j < 8; ++j) acc[i][j] = 0.f;

    for (int k0 = 0; k0 < 208; k0 += 16) {
        for (int idx = tid; idx < 2048; idx += 256) {
            int kk = idx & 15, mm = idx >> 4;
            int p = k0 + kk;
            As[kk][mm] = (p < HW) ? attn[(size_t)(m0 + mm) * HW + p] : 0.f;
        }
        for (int idx = tid; idx < 2048; idx += 256) {
            int kk = idx & 15, nn = idx >> 4;
            int p = k0 + kk;
            Bs[kk][nn] = (p < HW) ? feat[((size_t)b * DW + a0 + nn) * HW + p] : 0.f;
        }
        __syncthreads();
#pragma unroll
        for (int kk = 0; kk < 16; ++kk) {
            float av[8], bv[8];
#pragma unroll
            for (int j = 0; j < 8; ++j) av[j] = As[kk][ty + 16 * j];
#pragma unroll
            for (int j = 0; j < 8; ++j) bv[j] = Bs[kk][tx + 16 * j];
#pragma unroll
            for (int jr = 0; jr < 8; ++jr)
#pragma unroll
                for (int jc = 0; jc < 8; ++jc) acc[jr][jc] += av[jr] * bv[jc];
        }
        __syncthreads();
    }
#pragma unroll
    for (int jr = 0; jr < 8; ++jr) {
        int m = m0 + ty + 16 * jr;
#pragma unroll
        for (int jc = 0; jc < 8; ++jc) {
            int a = a0 + tx + 16 * jc;
            g_ctx[(size_t)m * DW + a] = acc[jr][jc];
        }
    }
}

// ================= fc2 + residuals, transposed output =================
__global__ void __launch_bounds__(256) fc2_kernel(const float* __restrict__ w,
                                                  const float* __restrict__ bias,
                                                  const float* __restrict__ x,
                                                  float* __restrict__ out) {
    __shared__ float As[16][132], Bs[16][132];
    int l0 = blockIdx.x * 128;
    int c0 = blockIdx.y * 128;
    int b = blockIdx.z;
    int tid = threadIdx.x, tx = tid & 15, ty = tid >> 4;
    float acc[8][8];
#pragma unroll
    for (int i = 0; i < 8; ++i)
#pragma unroll
        for (int j = 0; j < 8; ++j) acc[i][j] = 0.f;

    for (int k0 = 0; k0 < DW; k0 += 16) {
        for (int idx = tid; idx < 2048; idx += 256) {
            int kk = idx & 15, cc = idx >> 4;
            As[kk][cc] = w[(size_t)(c0 + cc) * DW + k0 + kk];
        }
        for (int idx = tid; idx < 2048; idx += 256) {
            int kk = idx & 15, ll = idx >> 4;
            Bs[kk][ll] = g_ctx[((size_t)b * Lr + l0 + ll) * DW + k0 + kk];
        }
        __syncthreads();
#pragma unroll
        for (int kk = 0; kk < 16; ++kk) {
            float av[8], bv[8];
#pragma unroll
            for (int j = 0; j < 8; ++j) av[j] = As[kk][ty + 16 * j];
#pragma unroll
            for (int j = 0; j < 8; ++j) bv[j] = Bs[kk][tx + 16 * j];
#pragma unroll
            for (int jr = 0; jr < 8; ++jr)
#pragma unroll
                for (int jc = 0; jc < 8; ++jc) acc[jr][jc] += av[jr] * bv[jc];
        }
        __syncthreads();
    }
#pragma unroll
    for (int jr = 0; jr < 8; ++jr) {
        int c = c0 + ty + 16 * jr;
        float bb = bias[c];
#pragma unroll
        for (int jc = 0; jc < 8; ++jc) {
            int l = l0 + tx + 16 * jc;
            size_t o = ((size_t)b * HALF + c) * Lr + l;
            out[o] = acc[jr][jc] + bb + g_h[o] + x[o];
        }
    }
}

// ================= launch =================
extern "C" void kernel_launch(void* const* d_in, const int* in_sizes, int n_in,
                              void* d_out, int out_size) {
    const float* x      = (const float*)d_in[0];
    const float* we     = (const float*)d_in[1];
    const float* img    = (const float*)d_in[2];
    // d_in[3] prev_attn unused by reference
    const float* conv_v = (const float*)d_in[4];
    const float* conv_g = (const float*)d_in[5];
    const float* conv_b = (const float*)d_in[6];
    const float* fc1_w  = (const float*)d_in[7];
    const float* fc1_b  = (const float*)d_in[8];
    const float* fc2_w  = (const float*)d_in[9];
    const float* fc2_b  = (const float*)d_in[10];

    float* out = (float*)d_out;
    const size_t SZ_OUT  = (size_t)Bn * HALF * Lr;   // 8388608
    const size_t SZ_WE   = (size_t)Bn * Lr * DW;     // 8388608
    const size_t SZ_IMG  = (size_t)Bn * DW * HW;     // 1605632
    float* out_we   = out + SZ_OUT;
    float* out_img  = out_we + SZ_WE;
    float* out_attn = out_img + SZ_IMG;

    wnorm_kernel<<<COUT, 256>>>(conv_v, conv_g);
    conv_kernel<<<dim3(Lr / 128, COUT / 128, Bn), 256>>>(x, conv_b);
    glu_kernel<<<(Bn * HALF * Lr) / 256, 256>>>();
    fc1_kernel<<<dim3(DW / 128, (Bn * Lr) / 128), 256>>>(fc1_w, fc1_b, we);
    score_kernel<<<dim3(2, (Bn * Lr) / 128), 256>>>(img);
    softmax_kernel<<<(Bn * Lr) / 8, 256>>>(out_attn);
    ctx_kernel<<<dim3(DW / 128, (Bn * Lr) / 128), 256>>>(out_attn, img);
    fc2_kernel<<<dim3(Lr / 128, HALF / 128, Bn), 256>>>(fc2_w, fc2_b, x, out);

    cudaMemcpyAsync(out_we, we, SZ_WE * sizeof(float), cudaMemcpyDeviceToDevice, 0);
    cudaMemcpyAsync(out_img, img, SZ_IMG * sizeof(float), cudaMemcpyDeviceToDevice, 0);
}

// round 5
// speedup vs baseline: 1.0923x; 1.0923x over previous
#include <cuda_runtime.h>
#include <math.h>

#define Bn   16
#define CIN  512
#define Lr   1024
#define COUT 1024
#define KW   5
#define DW   512
#define HW   196
#define HALF 512

typedef unsigned long long ull;

// ---- scratch (device globals; no allocation allowed) ----
__device__ float g_wn[COUT * CIN * KW];        // normalized conv weights
__device__ float g_y[(size_t)Bn * COUT * Lr];  // conv output (pre-GLU)
__device__ float g_h[(size_t)Bn * HALF * Lr];  // GLU output / identity_attn
__device__ float g_q[(size_t)Bn * Lr * DW];    // fc1 output + word_embed
__device__ float g_score[(size_t)Bn * Lr * HW];
__device__ float g_ctx[(size_t)Bn * Lr * DW];

// ---- packed f32x2 helpers ----
__device__ __forceinline__ void fma2(ull& acc, ull a, ull b) {
    asm("fma.rn.f32x2 %0, %1, %2, %0;" : "+l"(acc) : "l"(a), "l"(b));
}
__device__ __forceinline__ ull pk(float lo, float hi) {
    ull r;
    asm("mov.b64 %0, {%1, %2};" : "=l"(r) : "f"(lo), "f"(hi));
    return r;
}
__device__ __forceinline__ float2 upk(ull v) {
    float2 f;
    asm("mov.b64 {%0, %1}, %2;" : "=f"(f.x), "=f"(f.y) : "l"(v));
    return f;
}

// ================= weight norm =================
__global__ void wnorm_kernel(const float* __restrict__ v, const float* __restrict__ g) {
    int co = blockIdx.x;
    const float* vp = v + (size_t)co * (CIN * KW);
    float s = 0.f;
    for (int i = threadIdx.x; i < CIN * KW; i += blockDim.x) {
        float t = vp[i];
        s += t * t;
    }
    __shared__ float red[256];
    red[threadIdx.x] = s;
    __syncthreads();
    for (int o = 128; o > 0; o >>= 1) {
        if (threadIdx.x < o) red[threadIdx.x] += red[threadIdx.x + o];
        __syncthreads();
    }
    float scale = g[co] * rsqrtf(red[0]);
    for (int i = threadIdx.x; i < CIN * KW; i += blockDim.x)
        g_wn[(size_t)co * (CIN * KW) + i] = vp[i] * scale;
}

// ================= causal conv (tile 128co x 128l, packed 8x4 f32x2 reg tile) ===
__global__ void __launch_bounds__(256) conv_kernel(const float* __restrict__ x,
                                                   const float* __restrict__ bias) {
    __shared__ float2 Ws[128][41];  // [co_row][ci_local*5+t], value duplicated (w,w)
    __shared__ float Xs[8][136];    // [ci_local][l0-4+j]
    int l0 = blockIdx.x * 128;
    int co0 = blockIdx.y * 128;
    int b = blockIdx.z;
    int tid = threadIdx.x;
    int tx = tid & 15, ty = tid >> 4;
    const float* xb = x + (size_t)b * CIN * Lr;

    ull acc[8][4];
#pragma unroll
    for (int i = 0; i < 8; ++i)
#pragma unroll
        for (int j = 0; j < 4; ++j) acc[i][j] = 0ULL;

    for (int chunk = 0; chunk < 64; ++chunk) {
        int ci0 = chunk * 8;
        for (int idx = tid; idx < 40 * 128; idx += 256) {
            int kk = idx % 40, row = idx / 40;
            float v = g_wn[(size_t)(co0 + row) * (CIN * KW) + ci0 * KW + kk];
            Ws[row][kk] = make_float2(v, v);
        }
        for (int idx = tid; idx < 8 * 132; idx += 256) {
            int j = idx % 132, ci = idx / 132;
            int xp = l0 - 4 + j;
            Xs[ci][j] = (xp >= 0) ? xb[(size_t)(ci0 + ci) * Lr + xp] : 0.f;
        }
        __syncthreads();
        for (int ci = 0; ci < 8; ++ci) {
#pragma unroll
            for (int t = 0; t < 5; ++t) {
                ull wv[8], xv[4];
#pragma unroll
                for (int j = 0; j < 8; ++j)
                    wv[j] = *(const ull*)&Ws[ty + 16 * j][ci * 5 + t];
#pragma unroll
                for (int j = 0; j < 4; ++j)
                    xv[j] = pk(Xs[ci][2 * tx + 32 * j + t], Xs[ci][2 * tx + 1 + 32 * j + t]);
#pragma unroll
                for (int jr = 0; jr < 8; ++jr)
#pragma unroll
                    for (int jc = 0; jc < 4; ++jc) fma2(acc[jr][jc], wv[jr], xv[jc]);
            }
        }
        __syncthreads();
    }
#pragma unroll
    for (int jr = 0; jr < 8; ++jr) {
        int co = co0 + ty + 16 * jr;
        float bb = bias[co];
#pragma unroll
        for (int jc = 0; jc < 4; ++jc) {
            int l = l0 + 2 * tx + 32 * jc;
            float2 r = upk(acc[jr][jc]);
            r.x += bb;
            r.y += bb;
            *(float2*)&g_y[((size_t)b * COUT + co) * Lr + l] = r;
        }
    }
}

// ================= GLU (vectorized) =================
__global__ void glu_kernel() {
    size_t p = (size_t)blockIdx.x * 256 + threadIdx.x;  // over Bn*HALF*Lr/2
    size_t e = p * 2;
    int l = (int)(e & 1023);
    size_t rest = e >> 10;
    int c = (int)(rest & 511);
    int b = (int)(rest >> 9);
    float2 a = *(const float2*)&g_y[((size_t)b * COUT + c) * Lr + l];
    float2 g = *(const float2*)&g_y[((size_t)b * COUT + c + HALF) * Lr + l];
    float2 r;
    r.x = a.x * (1.f / (1.f + expf(-g.x)));
    r.y = a.y * (1.f / (1.f + expf(-g.y)));
    *(float2*)&g_h[e] = r;
}

// ====== packed GEMM inner block: A dup in As (float2), B scalar in Bs ======
#define GEMM_INNER()                                                        \
    _Pragma("unroll") for (int kk = 0; kk < 16; ++kk) {                     \
        ull av[8], bv[4];                                                   \
        _Pragma("unroll") for (int j = 0; j < 8; ++j)                       \
            av[j] = *(const ull*)&As[kk][ty + 16 * j];                      \
        _Pragma("unroll") for (int j = 0; j < 4; ++j)                       \
            bv[j] = *(const ull*)&Bs[kk][2 * tx + 32 * j];                  \
        _Pragma("unroll") for (int jr = 0; jr < 8; ++jr)                    \
            _Pragma("unroll") for (int jc = 0; jc < 4; ++jc)                \
                fma2(acc[jr][jc], av[jr], bv[jc]);                          \
    }

// ================= fc1: q = h^T W1^T + b1 + we =================
__global__ void __launch_bounds__(256) fc1_kernel(const float* __restrict__ w,
                                                  const float* __restrict__ bias,
                                                  const float* __restrict__ we) {
    __shared__ float2 As[16][130];  // dup rows (h values per m)
    __shared__ float Bs[16][132];
    int a0 = blockIdx.x * 128;
    int m0 = blockIdx.y * 128;
    int b = m0 >> 10, l0 = m0 & 1023;
    int tid = threadIdx.x, tx = tid & 15, ty = tid >> 4;
    ull acc[8][4];
#pragma unroll
    for (int i = 0; i < 8; ++i)
#pragma unroll
        for (int j = 0; j < 4; ++j) acc[i][j] = 0ULL;

    for (int k0 = 0; k0 < DW; k0 += 16) {
        for (int idx = tid; idx < 2048; idx += 256) {
            int mm = idx & 127, kk = idx >> 7;
            float v = g_h[((size_t)b * HALF + k0 + kk) * Lr + l0 + mm];
            As[kk][mm] = make_float2(v, v);
        }
        for (int idx = tid; idx < 2048; idx += 256) {
            int kk = idx & 15, nn = idx >> 4;
            Bs[kk][nn] = w[(size_t)(a0 + nn) * DW + k0 + kk];
        }
        __syncthreads();
        GEMM_INNER()
        __syncthreads();
    }
#pragma unroll
    for (int jr = 0; jr < 8; ++jr) {
        int m = m0 + ty + 16 * jr;
#pragma unroll
        for (int jc = 0; jc < 4; ++jc) {
            int a = a0 + 2 * tx + 32 * jc;
            float2 r = upk(acc[jr][jc]);
            float2 bb = *(const float2*)&bias[a];
            float2 ww = *(const float2*)&we[(size_t)m * DW + a];
            r.x += bb.x + ww.x;
            r.y += bb.y + ww.y;
            *(float2*)&g_q[(size_t)m * DW + a] = r;
        }
    }
}

// ================= score = q @ feat =================
__global__ void __launch_bounds__(256) score_kernel(const float* __restrict__ feat) {
    __shared__ float2 As[16][130];
    __shared__ float Bs[16][132];
    int p0 = blockIdx.x * 128;
    int m0 = blockIdx.y * 128;
    int b = m0 >> 10;
    int tid = threadIdx.x, tx = tid & 15, ty = tid >> 4;
    ull acc[8][4];
#pragma unroll
    for (int i = 0; i < 8; ++i)
#pragma unroll
        for (int j = 0; j < 4; ++j) acc[i][j] = 0ULL;

    for (int k0 = 0; k0 < DW; k0 += 16) {
        for (int idx = tid; idx < 2048; idx += 256) {
            int kk = idx & 15, mm = idx >> 4;
            float v = g_q[(size_t)(m0 + mm) * DW + k0 + kk];
            As[kk][mm] = make_float2(v, v);
        }
        for (int idx = tid; idx < 2048; idx += 256) {
            int nn = idx & 127, kk = idx >> 7;
            int p = p0 + nn;
            Bs[kk][nn] = (p < HW) ? feat[((size_t)b * DW + k0 + kk) * HW + p] : 0.f;
        }
        __syncthreads();
        GEMM_INNER()
        __syncthreads();
    }
#pragma unroll
    for (int jr = 0; jr < 8; ++jr) {
        int m = m0 + ty + 16 * jr;
#pragma unroll
        for (int jc = 0; jc < 4; ++jc) {
            int p = p0 + 2 * tx + 32 * jc;
            if (p < HW) {
                float2 r = upk(acc[jr][jc]);
                *(float2*)&g_score[(size_t)m * HW + p] = r;
            }
        }
    }
}

// ================= softmax over 196 (one warp per row) =================
__global__ void softmax_kernel(float* __restrict__ attn) {
    int warp = (blockIdx.x * blockDim.x + threadIdx.x) >> 5;
    int lane = threadIdx.x & 31;
    if (warp >= Bn * Lr) return;
    const float* sp = g_score + (size_t)warp * HW;
    float v[7];
    float mx = -1e30f;
#pragma unroll
    for (int i = 0; i < 7; ++i) {
        int p = lane + 32 * i;
        v[i] = (p < HW) ? sp[p] : -1e30f;
        mx = fmaxf(mx, v[i]);
    }
#pragma unroll
    for (int o = 16; o > 0; o >>= 1) mx = fmaxf(mx, __shfl_xor_sync(0xffffffffu, mx, o));
    float sum = 0.f;
#pragma unroll
    for (int i = 0; i < 7; ++i) {
        int p = lane + 32 * i;
        v[i] = (p < HW) ? expf(v[i] - mx) : 0.f;
        sum += v[i];
    }
#pragma unroll
    for (int o = 16; o > 0; o >>= 1) sum += __shfl_xor_sync(0xffffffffu, sum, o);
    float inv = 1.f / sum;
#pragma unroll
    for (int i = 0; i < 7; ++i) {
        int p = lane + 32 * i;
        if (p < HW) attn[(size_t)warp * HW + p] = v[i] * inv;
    }
}

// ================= ctx = attn @ feat^T =================
__global__ void __launch_bounds__(256) ctx_kernel(const float* __restrict__ attn,
                                                  const float* __restrict__ feat) {
    __shared__ float2 As[16][130];
    __shared__ float Bs[16][132];
    int a0 = blockIdx.x * 128;
    int m0 = blockIdx.y * 128;
    int b = m0 >> 10;
    int tid = threadIdx.x, tx = tid & 15, ty = tid >> 4;
    ull acc[8][4];
#pragma unroll
    for (int i = 0; i < 8; ++i)
#pragma unroll
        for (int j = 0; j < 4; ++j) acc[i][j] = 0ULL;

    for (int k0 = 0; k0 < 208; k0 += 16) {
        for (int idx = tid; idx < 2048; idx += 256) {
            int kk = idx & 15, mm = idx >> 4;
            int p = k0 + kk;
            float v = (p < HW) ? attn[(size_t)(m0 + mm) * HW + p] : 0.f;
            As[kk][mm] = make_float2(v, v);
        }
        for (int idx = tid; idx < 2048; idx += 256) {
            int kk = idx & 15, nn = idx >> 4;
            int p = k0 + kk;
            Bs[kk][nn] = (p < HW) ? feat[((size_t)b * DW + a0 + nn) * HW + p] : 0.f;
        }
        __syncthreads();
        GEMM_INNER()
        __syncthreads();
    }
#pragma unroll
    for (int jr = 0; jr < 8; ++jr) {
        int m = m0 + ty + 16 * jr;
#pragma unroll
        for (int jc = 0; jc < 4; ++jc) {
            int a = a0 + 2 * tx + 32 * jc;
            float2 r = upk(acc[jr][jc]);
            *(float2*)&g_ctx[(size_t)m * DW + a] = r;
        }
    }
}

// ================= fc2 + residuals, transposed output =================
__global__ void __launch_bounds__(256) fc2_kernel(const float* __restrict__ w,
                                                  const float* __restrict__ bias,
                                                  const float* __restrict__ x,
                                                  float* __restrict__ out) {
    __shared__ float2 As[16][130];  // dup rows (w per c)
    __shared__ float Bs[16][132];
    int l0 = blockIdx.x * 128;
    int c0 = blockIdx.y * 128;
    int b = blockIdx.z;
    int tid = threadIdx.x, tx = tid & 15, ty = tid >> 4;
    ull acc[8][4];
#pragma unroll
    for (int i = 0; i < 8; ++i)
#pragma unroll
        for (int j = 0; j < 4; ++j) acc[i][j] = 0ULL;

    for (int k0 = 0; k0 < DW; k0 += 16) {
        for (int idx = tid; idx < 2048; idx += 256) {
            int kk = idx & 15, cc = idx >> 4;
            float v = w[(size_t)(c0 + cc) * DW + k0 + kk];
            As[kk][cc] = make_float2(v, v);
        }
        for (int idx = tid; idx < 2048; idx += 256) {
            int kk = idx & 15, ll = idx >> 4;
            Bs[kk][ll] = g_ctx[((size_t)b * Lr + l0 + ll) * DW + k0 + kk];
        }
        __syncthreads();
        GEMM_INNER()
        __syncthreads();
    }
#pragma unroll
    for (int jr = 0; jr < 8; ++jr) {
        int c = c0 + ty + 16 * jr;
        float bb = bias[c];
#pragma unroll
        for (int jc = 0; jc < 4; ++jc) {
            int l = l0 + 2 * tx + 32 * jc;
            size_t o = ((size_t)b * HALF + c) * Lr + l;
            float2 r = upk(acc[jr][jc]);
            float2 hh = *(const float2*)&g_h[o];
            float2 xx = *(const float2*)&x[o];
            r.x += bb + hh.x + xx.x;
            r.y += bb + hh.y + xx.y;
            *(float2*)&out[o] = r;
        }
    }
}

// ================= launch =================
extern "C" void kernel_launch(void* const* d_in, const int* in_sizes, int n_in,
                              void* d_out, int out_size) {
    const float* x      = (const float*)d_in[0];
    const float* we     = (const float*)d_in[1];
    const float* img    = (const float*)d_in[2];
    // d_in[3] prev_attn unused by reference
    const float* conv_v = (const float*)d_in[4];
    const float* conv_g = (const float*)d_in[5];
    const float* conv_b = (const float*)d_in[6];
    const float* fc1_w  = (const float*)d_in[7];
    const float* fc1_b  = (const float*)d_in[8];
    const float* fc2_w  = (const float*)d_in[9];
    const float* fc2_b  = (const float*)d_in[10];

    float* out = (float*)d_out;
    const size_t SZ_OUT  = (size_t)Bn * HALF * Lr;   // 8388608
    const size_t SZ_WE   = (size_t)Bn * Lr * DW;     // 8388608
    const size_t SZ_IMG  = (size_t)Bn * DW * HW;     // 1605632
    float* out_we   = out + SZ_OUT;
    float* out_img  = out_we + SZ_WE;
    float* out_attn = out_img + SZ_IMG;

    wnorm_kernel<<<COUT, 256>>>(conv_v, conv_g);
    conv_kernel<<<dim3(Lr / 128, COUT / 128, Bn), 256>>>(x, conv_b);
    glu_kernel<<<(Bn * HALF * Lr) / 512, 256>>>();
    fc1_kernel<<<dim3(DW / 128, (Bn * Lr) / 128), 256>>>(fc1_w, fc1_b, we);
    score_kernel<<<dim3(2, (Bn * Lr) / 128), 256>>>(img);
    softmax_kernel<<<(Bn * Lr) / 8, 256>>>(out_attn);
    ctx_kernel<<<dim3(DW / 128, (Bn * Lr) / 128), 256>>>(out_attn, img);
    fc2_kernel<<<dim3(Lr / 128, HALF / 128, Bn), 256>>>(fc2_w, fc2_b, x, out);

    cudaMemcpyAsync(out_we, we, SZ_WE * sizeof(float), cudaMemcpyDeviceToDevice, 0);
    cudaMemcpyAsync(out_img, img, SZ_IMG * sizeof(float), cudaMemcpyDeviceToDevice, 0);
}

// round 6
// speedup vs baseline: 1.4245x; 1.3041x over previous
#include <cuda_runtime.h>
#include <math.h>

#define Bn   16
#define CIN  512
#define Lr   1024
#define COUT 1024
#define KW   5
#define DW   512
#define HW   196
#define HALF 512

// ---- scratch (device globals; no allocation allowed) ----
__device__ float g_wn[COUT * CIN * KW];        // normalized conv weights
__device__ float g_y[(size_t)Bn * COUT * Lr];  // conv output (pre-GLU)
__device__ float g_h[(size_t)Bn * HALF * Lr];  // GLU output / identity_attn
__device__ float g_q[(size_t)Bn * Lr * DW];    // fc1 output + word_embed
__device__ float g_score[(size_t)Bn * Lr * HW];
__device__ float g_ctx[(size_t)Bn * Lr * DW];

// ---- tf32 helpers ----
__device__ __forceinline__ unsigned f2tf(float f) {
    unsigned r;
    asm("cvt.rna.tf32.f32 %0, %1;" : "=r"(r) : "f"(f));
    return r;
}
__device__ __forceinline__ float tff(unsigned u) { return __uint_as_float(u); }

__device__ __forceinline__ void mma_tf32(float* c, const unsigned* a, const unsigned* b) {
    asm volatile(
        "mma.sync.aligned.m16n8k8.row.col.f32.tf32.tf32.f32 "
        "{%0,%1,%2,%3}, {%4,%5,%6,%7}, {%8,%9}, {%0,%1,%2,%3};"
        : "+f"(c[0]), "+f"(c[1]), "+f"(c[2]), "+f"(c[3])
        : "r"(a[0]), "r"(a[1]), "r"(a[2]), "r"(a[3]), "r"(b[0]), "r"(b[1]));
}

// One 16-wide k-chunk of the 128x128 block: warp computes 64x32 via 4x4 mma tiles,
// with 3xTF32 split for fp32-class accuracy.
__device__ __forceinline__ void mma_chunk(const float (*As)[20], const float (*Bs)[20],
                                          int wm, int wn, int lane,
                                          float acc[4][4][4]) {
    int r = lane >> 2;
#pragma unroll
    for (int ks = 0; ks < 2; ++ks) {
        int kc = ks * 8 + (lane & 3);
        unsigned ah[4][4], al[4][4], bh[4][2], bl[4][2];
#pragma unroll
        for (int i = 0; i < 4; ++i) {
            int r0 = wm + i * 16 + r;
            float f0 = As[r0][kc], f1 = As[r0 + 8][kc];
            float f2 = As[r0][kc + 4], f3 = As[r0 + 8][kc + 4];
            ah[i][0] = f2tf(f0); al[i][0] = f2tf(f0 - tff(ah[i][0]));
            ah[i][1] = f2tf(f1); al[i][1] = f2tf(f1 - tff(ah[i][1]));
            ah[i][2] = f2tf(f2); al[i][2] = f2tf(f2 - tff(ah[i][2]));
            ah[i][3] = f2tf(f3); al[i][3] = f2tf(f3 - tff(ah[i][3]));
        }
#pragma unroll
        for (int j = 0; j < 4; ++j) {
            int n0 = wn + j * 8 + r;
            float g0 = Bs[n0][kc], g1 = Bs[n0][kc + 4];
            bh[j][0] = f2tf(g0); bl[j][0] = f2tf(g0 - tff(bh[j][0]));
            bh[j][1] = f2tf(g1); bl[j][1] = f2tf(g1 - tff(bh[j][1]));
        }
#pragma unroll
        for (int i = 0; i < 4; ++i)
#pragma unroll
            for (int j = 0; j < 4; ++j) {
                mma_tf32(acc[i][j], ah[i], bh[j]);
                mma_tf32(acc[i][j], ah[i], bl[j]);
                mma_tf32(acc[i][j], al[i], bh[j]);
            }
    }
}

#define ACC_INIT()                                   \
    float acc[4][4][4];                              \
    _Pragma("unroll") for (int i = 0; i < 4; ++i)    \
        _Pragma("unroll") for (int j = 0; j < 4; ++j)\
            _Pragma("unroll") for (int t = 0; t < 4; ++t) acc[i][j][t] = 0.f;

// ================= weight norm =================
__global__ void wnorm_kernel(const float* __restrict__ v, const float* __restrict__ g) {
    int co = blockIdx.x;
    const float* vp = v + (size_t)co * (CIN * KW);
    float s = 0.f;
    for (int i = threadIdx.x; i < CIN * KW; i += blockDim.x) {
        float t = vp[i];
        s += t * t;
    }
    __shared__ float red[256];
    red[threadIdx.x] = s;
    __syncthreads();
    for (int o = 128; o > 0; o >>= 1) {
        if (threadIdx.x < o) red[threadIdx.x] += red[threadIdx.x + o];
        __syncthreads();
    }
    float scale = g[co] * rsqrtf(red[0]);
    for (int i = threadIdx.x; i < CIN * KW; i += blockDim.x)
        g_wn[(size_t)co * (CIN * KW) + i] = vp[i] * scale;
}

// ================= causal conv as 5 shifted GEMMs (tensor core) =================
__global__ void __launch_bounds__(256) conv_kernel(const float* __restrict__ x,
                                                   const float* __restrict__ bias) {
    __shared__ float As[2][128][20];  // [co][ci_chunk]
    __shared__ float Bs[2][128][20];  // [l][ci_chunk]
    int tid = threadIdx.x, lane = tid & 31, wid = tid >> 5;
    int wm = (wid & 1) * 64, wn = (wid >> 1) * 32;
    int l0 = blockIdx.x * 128, co0 = blockIdx.y * 128, b = blockIdx.z;
    ACC_INIT();
    float pa[8], pb[8];
    const int NC = 160;  // 5 taps * 32 ci-chunks

    auto prefetch = [&](int c) {
        int t = c >> 5, ci0 = (c & 31) << 4;
#pragma unroll
        for (int s = 0; s < 8; ++s) {
            int e = s * 256 + tid;
            pa[s] = g_wn[(size_t)(co0 + (e >> 4)) * (CIN * KW) + (ci0 + (e & 15)) * KW + t];
        }
#pragma unroll
        for (int s = 0; s < 8; ++s) {
            int e = s * 256 + tid;
            int xp = l0 + (e & 127) + t - 4;
            pb[s] = (xp >= 0) ? x[((size_t)b * CIN + ci0 + (e >> 7)) * Lr + xp] : 0.f;
        }
    };
    auto commit = [&](int buf) {
#pragma unroll
        for (int s = 0; s < 8; ++s) {
            int e = s * 256 + tid;
            As[buf][e >> 4][e & 15] = pa[s];
            Bs[buf][e & 127][e >> 7] = pb[s];
        }
    };

    prefetch(0);
    commit(0);
    __syncthreads();
    for (int c = 0; c < NC; ++c) {
        if (c + 1 < NC) prefetch(c + 1);
        mma_chunk(As[c & 1], Bs[c & 1], wm, wn, lane, acc);
        if (c + 1 < NC) commit((c + 1) & 1);
        __syncthreads();
    }

    int r = lane >> 2;
#pragma unroll
    for (int i = 0; i < 4; ++i) {
        int co = co0 + wm + i * 16 + r;
        float b0 = bias[co], b1 = bias[co + 8];
#pragma unroll
        for (int j = 0; j < 4; ++j) {
            int l = l0 + wn + j * 8 + (lane & 3) * 2;
            float2 v0 = make_float2(acc[i][j][0] + b0, acc[i][j][1] + b0);
            float2 v1 = make_float2(acc[i][j][2] + b1, acc[i][j][3] + b1);
            *(float2*)&g_y[((size_t)b * COUT + co) * Lr + l] = v0;
            *(float2*)&g_y[((size_t)b * COUT + co + 8) * Lr + l] = v1;
        }
    }
}

// ================= GLU (vectorized) =================
__global__ void glu_kernel() {
    size_t p = (size_t)blockIdx.x * 256 + threadIdx.x;
    size_t e = p * 2;
    int l = (int)(e & 1023);
    size_t rest = e >> 10;
    int c = (int)(rest & 511);
    int b = (int)(rest >> 9);
    float2 a = *(const float2*)&g_y[((size_t)b * COUT + c) * Lr + l];
    float2 g = *(const float2*)&g_y[((size_t)b * COUT + c + HALF) * Lr + l];
    float2 r;
    r.x = a.x * (1.f / (1.f + expf(-g.x)));
    r.y = a.y * (1.f / (1.f + expf(-g.y)));
    *(float2*)&g_h[e] = r;
}

// ================= fc1: q = h^T W1^T + b1 + we =================
__global__ void __launch_bounds__(256) fc1_kernel(const float* __restrict__ w,
                                                  const float* __restrict__ bias,
                                                  const float* __restrict__ we) {
    __shared__ float As[2][128][20];  // [m=l][k]
    __shared__ float Bs[2][128][20];  // [n=a][k]
    int tid = threadIdx.x, lane = tid & 31, wid = tid >> 5;
    int wm = (wid & 1) * 64, wn = (wid >> 1) * 32;
    int a0 = blockIdx.x * 128, m0 = blockIdx.y * 128;
    int b = m0 >> 10, l0 = m0 & 1023;
    ACC_INIT();
    float pa[8], pb[8];
    const int NC = DW / 16;

    auto prefetch = [&](int c) {
#pragma unroll
        for (int s = 0; s < 8; ++s) {
            int e = s * 256 + tid;
            pa[s] = g_h[((size_t)b * HALF + c * 16 + (e >> 7)) * Lr + l0 + (e & 127)];
        }
#pragma unroll
        for (int s = 0; s < 8; ++s) {
            int e = s * 256 + tid;
            pb[s] = w[(size_t)(a0 + (e >> 4)) * DW + c * 16 + (e & 15)];
        }
    };
    auto commit = [&](int buf) {
#pragma unroll
        for (int s = 0; s < 8; ++s) {
            int e = s * 256 + tid;
            As[buf][e & 127][e >> 7] = pa[s];
            Bs[buf][e >> 4][e & 15] = pb[s];
        }
    };

    prefetch(0);
    commit(0);
    __syncthreads();
    for (int c = 0; c < NC; ++c) {
        if (c + 1 < NC) prefetch(c + 1);
        mma_chunk(As[c & 1], Bs[c & 1], wm, wn, lane, acc);
        if (c + 1 < NC) commit((c + 1) & 1);
        __syncthreads();
    }

    int r = lane >> 2;
#pragma unroll
    for (int i = 0; i < 4; ++i) {
        int m = m0 + wm + i * 16 + r;
#pragma unroll
        for (int j = 0; j < 4; ++j) {
            int a = a0 + wn + j * 8 + (lane & 3) * 2;
            float2 bb = *(const float2*)&bias[a];
            float2 w0 = *(const float2*)&we[(size_t)m * DW + a];
            float2 w1 = *(const float2*)&we[(size_t)(m + 8) * DW + a];
            float2 v0 = make_float2(acc[i][j][0] + bb.x + w0.x, acc[i][j][1] + bb.y + w0.y);
            float2 v1 = make_float2(acc[i][j][2] + bb.x + w1.x, acc[i][j][3] + bb.y + w1.y);
            *(float2*)&g_q[(size_t)m * DW + a] = v0;
            *(float2*)&g_q[(size_t)(m + 8) * DW + a] = v1;
        }
    }
}

// ================= score = q @ feat =================
__global__ void __launch_bounds__(256) score_kernel(const float* __restrict__ feat) {
    __shared__ float As[2][128][20];  // [m][k=a]
    __shared__ float Bs[2][128][20];  // [n=p][k=a]
    int tid = threadIdx.x, lane = tid & 31, wid = tid >> 5;
    int wm = (wid & 1) * 64, wn = (wid >> 1) * 32;
    int p0 = blockIdx.x * 128, m0 = blockIdx.y * 128;
    int b = m0 >> 10;
    ACC_INIT();
    float pa[8], pb[8];
    const int NC = DW / 16;

    auto prefetch = [&](int c) {
#pragma unroll
        for (int s = 0; s < 8; ++s) {
            int e = s * 256 + tid;
            pa[s] = g_q[(size_t)(m0 + (e >> 4)) * DW + c * 16 + (e & 15)];
        }
#pragma unroll
        for (int s = 0; s < 8; ++s) {
            int e = s * 256 + tid;
            int p = p0 + (e & 127);
            pb[s] = (p < HW) ? feat[((size_t)b * DW + c * 16 + (e >> 7)) * HW + p] : 0.f;
        }
    };
    auto commit = [&](int buf) {
#pragma unroll
        for (int s = 0; s < 8; ++s) {
            int e = s * 256 + tid;
            As[buf][e >> 4][e & 15] = pa[s];
            Bs[buf][e & 127][e >> 7] = pb[s];
        }
    };

    prefetch(0);
    commit(0);
    __syncthreads();
    for (int c = 0; c < NC; ++c) {
        if (c + 1 < NC) prefetch(c + 1);
        mma_chunk(As[c & 1], Bs[c & 1], wm, wn, lane, acc);
        if (c + 1 < NC) commit((c + 1) & 1);
        __syncthreads();
    }

    int r = lane >> 2;
#pragma unroll
    for (int i = 0; i < 4; ++i) {
        int m = m0 + wm + i * 16 + r;
#pragma unroll
        for (int j = 0; j < 4; ++j) {
            int p = p0 + wn + j * 8 + (lane & 3) * 2;
            if (p < HW) {
                *(float2*)&g_score[(size_t)m * HW + p] =
                    make_float2(acc[i][j][0], acc[i][j][1]);
                *(float2*)&g_score[(size_t)(m + 8) * HW + p] =
                    make_float2(acc[i][j][2], acc[i][j][3]);
            }
        }
    }
}

// ================= softmax over 196 (one warp per row) =================
__global__ void softmax_kernel(float* __restrict__ attn) {
    int warp = (blockIdx.x * blockDim.x + threadIdx.x) >> 5;
    int lane = threadIdx.x & 31;
    if (warp >= Bn * Lr) return;
    const float* sp = g_score + (size_t)warp * HW;
    float v[7];
    float mx = -1e30f;
#pragma unroll
    for (int i = 0; i < 7; ++i) {
        int p = lane + 32 * i;
        v[i] = (p < HW) ? sp[p] : -1e30f;
        mx = fmaxf(mx, v[i]);
    }
#pragma unroll
    for (int o = 16; o > 0; o >>= 1) mx = fmaxf(mx, __shfl_xor_sync(0xffffffffu, mx, o));
    float sum = 0.f;
#pragma unroll
    for (int i = 0; i < 7; ++i) {
        int p = lane + 32 * i;
        v[i] = (p < HW) ? expf(v[i] - mx) : 0.f;
        sum += v[i];
    }
#pragma unroll
    for (int o = 16; o > 0; o >>= 1) sum += __shfl_xor_sync(0xffffffffu, sum, o);
    float inv = 1.f / sum;
#pragma unroll
    for (int i = 0; i < 7; ++i) {
        int p = lane + 32 * i;
        if (p < HW) attn[(size_t)warp * HW + p] = v[i] * inv;
    }
}

// ================= ctx = attn @ feat^T =================
__global__ void __launch_bounds__(256) ctx_kernel(const float* __restrict__ attn,
                                                  const float* __restrict__ feat) {
    __shared__ float As[2][128][20];  // [m][k=p]
    __shared__ float Bs[2][128][20];  // [n=a][k=p]
    int tid = threadIdx.x, lane = tid & 31, wid = tid >> 5;
    int wm = (wid & 1) * 64, wn = (wid >> 1) * 32;
    int a0 = blockIdx.x * 128, m0 = blockIdx.y * 128;
    int b = m0 >> 10;
    ACC_INIT();
    float pa[8], pb[8];
    const int NC = 13;  // ceil(196/16)

    auto prefetch = [&](int c) {
#pragma unroll
        for (int s = 0; s < 8; ++s) {
            int e = s * 256 + tid;
            int kp = c * 16 + (e & 15);
            pa[s] = (kp < HW) ? attn[(size_t)(m0 + (e >> 4)) * HW + kp] : 0.f;
        }
#pragma unroll
        for (int s = 0; s < 8; ++s) {
            int e = s * 256 + tid;
            int kp = c * 16 + (e & 15);
            pb[s] = (kp < HW) ? feat[((size_t)b * DW + a0 + (e >> 4)) * HW + kp] : 0.f;
        }
    };
    auto commit = [&](int buf) {
#pragma unroll
        for (int s = 0; s < 8; ++s) {
            int e = s * 256 + tid;
            As[buf][e >> 4][e & 15] = pa[s];
            Bs[buf][e >> 4][e & 15] = pb[s];
        }
    };

    prefetch(0);
    commit(0);
    __syncthreads();
    for (int c = 0; c < NC; ++c) {
        if (c + 1 < NC) prefetch(c + 1);
        mma_chunk(As[c & 1], Bs[c & 1], wm, wn, lane, acc);
        if (c + 1 < NC) commit((c + 1) & 1);
        __syncthreads();
    }

    int r = lane >> 2;
#pragma unroll
    for (int i = 0; i < 4; ++i) {
        int m = m0 + wm + i * 16 + r;
#pragma unroll
        for (int j = 0; j < 4; ++j) {
            int a = a0 + wn + j * 8 + (lane & 3) * 2;
            *(float2*)&g_ctx[(size_t)m * DW + a] = make_float2(acc[i][j][0], acc[i][j][1]);
            *(float2*)&g_ctx[(size_t)(m + 8) * DW + a] = make_float2(acc[i][j][2], acc[i][j][3]);
        }
    }
}

// ================= fc2 + residuals, transposed output =================
__global__ void __launch_bounds__(256) fc2_kernel(const float* __restrict__ w,
                                                  const float* __restrict__ bias,
                                                  const float* __restrict__ x,
                                                  float* __restrict__ out) {
    __shared__ float As[2][128][20];  // [m=c][k=a]
    __shared__ float Bs[2][128][20];  // [n=l][k=a]
    int tid = threadIdx.x, lane = tid & 31, wid = tid >> 5;
    int wm = (wid & 1) * 64, wn = (wid >> 1) * 32;
    int l0 = blockIdx.x * 128, c0 = blockIdx.y * 128, b = blockIdx.z;
    ACC_INIT();
    float pa[8], pb[8];
    const int NC = DW / 16;

    auto prefetch = [&](int c) {
#pragma unroll
        for (int s = 0; s < 8; ++s) {
            int e = s * 256 + tid;
            pa[s] = w[(size_t)(c0 + (e >> 4)) * DW + c * 16 + (e & 15)];
        }
#pragma unroll
        for (int s = 0; s < 8; ++s) {
            int e = s * 256 + tid;
            pb[s] = g_ctx[((size_t)b * Lr + l0 + (e >> 4)) * DW + c * 16 + (e & 15)];
        }
    };
    auto commit = [&](int buf) {
#pragma unroll
        for (int s = 0; s < 8; ++s) {
            int e = s * 256 + tid;
            As[buf][e >> 4][e & 15] = pa[s];
            Bs[buf][e >> 4][e & 15] = pb[s];
        }
    };

    prefetch(0);
    commit(0);
    __syncthreads();
    for (int c = 0; c < NC; ++c) {
        if (c + 1 < NC) prefetch(c + 1);
        mma_chunk(As[c & 1], Bs[c & 1], wm, wn, lane, acc);
        if (c + 1 < NC) commit((c + 1) & 1);
        __syncthreads();
    }

    int r = lane >> 2;
#pragma unroll
    for (int i = 0; i < 4; ++i) {
        int cc = c0 + wm + i * 16 + r;
        float b0 = bias[cc], b1 = bias[cc + 8];
#pragma unroll
        for (int j = 0; j < 4; ++j) {
            int l = l0 + wn + j * 8 + (lane & 3) * 2;
            size_t o0 = ((size_t)b * HALF + cc) * Lr + l;
            size_t o1 = ((size_t)b * HALF + cc + 8) * Lr + l;
            float2 h0 = *(const float2*)&g_h[o0];
            float2 x0 = *(const float2*)&x[o0];
            float2 h1 = *(const float2*)&g_h[o1];
            float2 x1 = *(const float2*)&x[o1];
            *(float2*)&out[o0] = make_float2(acc[i][j][0] + b0 + h0.x + x0.x,
                                             acc[i][j][1] + b0 + h0.y + x0.y);
            *(float2*)&out[o1] = make_float2(acc[i][j][2] + b1 + h1.x + x1.x,
                                             acc[i][j][3] + b1 + h1.y + x1.y);
        }
    }
}

// ================= launch =================
extern "C" void kernel_launch(void* const* d_in, const int* in_sizes, int n_in,
                              void* d_out, int out_size) {
    const float* x      = (const float*)d_in[0];
    const float* we     = (const float*)d_in[1];
    const float* img    = (const float*)d_in[2];
    // d_in[3] prev_attn unused by reference
    const float* conv_v = (const float*)d_in[4];
    const float* conv_g = (const float*)d_in[5];
    const float* conv_b = (const float*)d_in[6];
    const float* fc1_w  = (const float*)d_in[7];
    const float* fc1_b  = (const float*)d_in[8];
    const float* fc2_w  = (const float*)d_in[9];
    const float* fc2_b  = (const float*)d_in[10];

    float* out = (float*)d_out;
    const size_t SZ_OUT = (size_t)Bn * HALF * Lr;  // 8388608
    const size_t SZ_WE  = (size_t)Bn * Lr * DW;    // 8388608
    const size_t SZ_IMG = (size_t)Bn * DW * HW;    // 1605632
    float* out_we   = out + SZ_OUT;
    float* out_img  = out_we + SZ_WE;
    float* out_attn = out_img + SZ_IMG;

    wnorm_kernel<<<COUT, 256>>>(conv_v, conv_g);
    conv_kernel<<<dim3(Lr / 128, COUT / 128, Bn), 256>>>(x, conv_b);
    glu_kernel<<<(Bn * HALF * Lr) / 512, 256>>>();
    fc1_kernel<<<dim3(DW / 128, (Bn * Lr) / 128), 256>>>(fc1_w, fc1_b, we);
    score_kernel<<<dim3(2, (Bn * Lr) / 128), 256>>>(img);
    softmax_kernel<<<(Bn * Lr) / 8, 256>>>(out_attn);
    ctx_kernel<<<dim3(DW / 128, (Bn * Lr) / 128), 256>>>(out_attn, img);
    fc2_kernel<<<dim3(Lr / 128, HALF / 128, Bn), 256>>>(fc2_w, fc2_b, x, out);

    cudaMemcpyAsync(out_we, we, SZ_WE * sizeof(float), cudaMemcpyDeviceToDevice, 0);
    cudaMemcpyAsync(out_img, img, SZ_IMG * sizeof(float), cudaMemcpyDeviceToDevice, 0);
}

// round 7
// speedup vs baseline: 2.1794x; 1.5300x over previous
#include <cuda_runtime.h>
#include <math.h>

#define Bn   16
#define CIN  512
#define Lr   1024
#define COUT 1024
#define KW   5
#define DW   512
#define HW   196
#define HALF 512

typedef unsigned uint_t;

// ---- scratch (device globals; no allocation allowed) ----
__device__ float g_wn[COUT * CIN * KW];        // normalized conv weights
__device__ float g_y[(size_t)Bn * COUT * Lr];  // conv output (pre-GLU)
__device__ float g_h[(size_t)Bn * HALF * Lr];  // GLU output / identity_attn
__device__ float g_q[(size_t)Bn * Lr * DW];    // fc1 output + word_embed
__device__ float g_score[(size_t)Bn * Lr * HW];
__device__ float g_ctx[(size_t)Bn * Lr * DW];

// ---- bf16x3 split helpers ----
// pack two fp32 into bf16x2 (lo half = v0, hi half = v1)
__device__ __forceinline__ void split2(float v0, float v1, uint_t& hi, uint_t& lo) {
    asm("cvt.rn.bf16x2.f32 %0, %1, %2;" : "=r"(hi) : "f"(v1), "f"(v0));
    float h0 = __uint_as_float(hi << 16);
    float h1 = __uint_as_float(hi & 0xffff0000u);
    asm("cvt.rn.bf16x2.f32 %0, %1, %2;" : "=r"(lo) : "f"(v1 - h1), "f"(v0 - h0));
}

__device__ __forceinline__ void mma_bf16(float* c, const uint_t* a, const uint_t* b) {
    asm volatile(
        "mma.sync.aligned.m16n8k16.row.col.f32.bf16.bf16.f32 "
        "{%0,%1,%2,%3}, {%4,%5,%6,%7}, {%8,%9}, {%0,%1,%2,%3};"
        : "+f"(c[0]), "+f"(c[1]), "+f"(c[2]), "+f"(c[3])
        : "r"(a[0]), "r"(a[1]), "r"(a[2]), "r"(a[3]), "r"(b[0]), "r"(b[1]));
}

#define PAD 12  // words per row: bases {12r mod 32} hit all banks once -> conflict-free

// One 16-wide k-chunk: warp computes 64x32 via 4x4 m16n8k16 tiles, 3-term bf16 split.
__device__ __forceinline__ void mma_chunk(const uint_t (*Ah)[PAD], const uint_t (*Al)[PAD],
                                          const uint_t (*Bh)[PAD], const uint_t (*Bl)[PAD],
                                          int wm, int wn, int lane, float acc[4][4][4]) {
    int r = lane >> 2, t = lane & 3;
    uint_t ah[4][4], al[4][4], bh[4][2], bl[4][2];
#pragma unroll
    for (int i = 0; i < 4; ++i) {
        int r0 = wm + i * 16 + r;
        ah[i][0] = Ah[r0][t];     ah[i][1] = Ah[r0 + 8][t];
        ah[i][2] = Ah[r0][4 + t]; ah[i][3] = Ah[r0 + 8][4 + t];
        al[i][0] = Al[r0][t];     al[i][1] = Al[r0 + 8][t];
        al[i][2] = Al[r0][4 + t]; al[i][3] = Al[r0 + 8][4 + t];
    }
#pragma unroll
    for (int j = 0; j < 4; ++j) {
        int n0 = wn + j * 8 + r;
        bh[j][0] = Bh[n0][t]; bh[j][1] = Bh[n0][4 + t];
        bl[j][0] = Bl[n0][t]; bl[j][1] = Bl[n0][4 + t];
    }
#pragma unroll
    for (int i = 0; i < 4; ++i)
#pragma unroll
        for (int j = 0; j < 4; ++j) {
            mma_bf16(acc[i][j], ah[i], bh[j]);
            mma_bf16(acc[i][j], ah[i], bl[j]);
            mma_bf16(acc[i][j], al[i], bh[j]);
        }
}

#define ACC_INIT()                                    \
    float acc[4][4][4];                               \
    _Pragma("unroll") for (int i = 0; i < 4; ++i)     \
        _Pragma("unroll") for (int j = 0; j < 4; ++j) \
            _Pragma("unroll") for (int t = 0; t < 4; ++t) acc[i][j][t] = 0.f;

#define SMEM_DECL()                  \
    __shared__ uint_t Ah[2][128][PAD], Al[2][128][PAD]; \
    __shared__ uint_t Bh[2][128][PAD], Bl[2][128][PAD];

// commit staged float2 pairs (4 per tile per thread) into split smem
#define COMMIT(buf)                                            \
    _Pragma("unroll") for (int s = 0; s < 4; ++s) {            \
        int p = s * 256 + tid;                                 \
        int row = p >> 3, kp = p & 7;                          \
        uint_t hi, lo;                                         \
        split2(sa[s].x, sa[s].y, hi, lo);                      \
        Ah[buf][row][kp] = hi;                                 \
        Al[buf][row][kp] = lo;                                 \
        split2(sb[s].x, sb[s].y, hi, lo);                      \
        Bh[buf][row][kp] = hi;                                 \
        Bl[buf][row][kp] = lo;                                 \
    }

// ================= weight norm =================
__global__ void wnorm_kernel(const float* __restrict__ v, const float* __restrict__ g) {
    int co = blockIdx.x;
    const float* vp = v + (size_t)co * (CIN * KW);
    float s = 0.f;
    for (int i = threadIdx.x; i < CIN * KW; i += blockDim.x) {
        float t = vp[i];
        s += t * t;
    }
    __shared__ float red[256];
    red[threadIdx.x] = s;
    __syncthreads();
    for (int o = 128; o > 0; o >>= 1) {
        if (threadIdx.x < o) red[threadIdx.x] += red[threadIdx.x + o];
        __syncthreads();
    }
    float scale = g[co] * rsqrtf(red[0]);
    for (int i = threadIdx.x; i < CIN * KW; i += blockDim.x)
        g_wn[(size_t)co * (CIN * KW) + i] = vp[i] * scale;
}

// ================= causal conv as 5 shifted GEMMs (bf16x3 tensor core) ==========
__global__ void __launch_bounds__(256) conv_kernel(const float* __restrict__ x,
                                                   const float* __restrict__ bias) {
    SMEM_DECL();
    int tid = threadIdx.x, lane = tid & 31, wid = tid >> 5;
    int wm = (wid & 1) * 64, wn = (wid >> 1) * 32;
    int l0 = blockIdx.x * 128, co0 = blockIdx.y * 128, b = blockIdx.z;
    ACC_INIT();
    float2 sa[4], sb[4];
    const int NC = 160;  // 5 taps * 32 ci-chunks of 16

    auto prefetch = [&](int c) {
        int t = c >> 5, ci0 = (c & 31) << 4;
#pragma unroll
        for (int s = 0; s < 4; ++s) {
            int p = s * 256 + tid;
            int row = p >> 3, kp = p & 7;
            size_t base = (size_t)(co0 + row) * (CIN * KW) + (ci0 + 2 * kp) * KW + t;
            sa[s].x = g_wn[base];
            sa[s].y = g_wn[base + KW];
            int xp = l0 + row + t - 4;
            if (xp >= 0) {
                size_t xb = ((size_t)b * CIN + ci0 + 2 * kp) * Lr + xp;
                sb[s].x = x[xb];
                sb[s].y = x[xb + Lr];
            } else {
                sb[s] = make_float2(0.f, 0.f);
            }
        }
    };

    prefetch(0);
    COMMIT(0)
    __syncthreads();
    for (int c = 0; c < NC; ++c) {
        if (c + 1 < NC) prefetch(c + 1);
        mma_chunk(Ah[c & 1], Al[c & 1], Bh[c & 1], Bl[c & 1], wm, wn, lane, acc);
        if (c + 1 < NC) { int nb = (c + 1) & 1; COMMIT(nb) }
        __syncthreads();
    }

    int r = lane >> 2;
#pragma unroll
    for (int i = 0; i < 4; ++i) {
        int co = co0 + wm + i * 16 + r;
        float b0 = bias[co], b1 = bias[co + 8];
#pragma unroll
        for (int j = 0; j < 4; ++j) {
            int l = l0 + wn + j * 8 + (lane & 3) * 2;
            *(float2*)&g_y[((size_t)b * COUT + co) * Lr + l] =
                make_float2(acc[i][j][0] + b0, acc[i][j][1] + b0);
            *(float2*)&g_y[((size_t)b * COUT + co + 8) * Lr + l] =
                make_float2(acc[i][j][2] + b1, acc[i][j][3] + b1);
        }
    }
}

// ================= GLU (vectorized) =================
__global__ void glu_kernel() {
    size_t p = (size_t)blockIdx.x * 256 + threadIdx.x;
    size_t e = p * 2;
    int l = (int)(e & 1023);
    size_t rest = e >> 10;
    int c = (int)(rest & 511);
    int b = (int)(rest >> 9);
    float2 a = *(const float2*)&g_y[((size_t)b * COUT + c) * Lr + l];
    float2 g = *(const float2*)&g_y[((size_t)b * COUT + c + HALF) * Lr + l];
    float2 r;
    r.x = a.x * (1.f / (1.f + expf(-g.x)));
    r.y = a.y * (1.f / (1.f + expf(-g.y)));
    *(float2*)&g_h[e] = r;
}

// ================= fc1: q = h^T W1^T + b1 + we =================
__global__ void __launch_bounds__(256) fc1_kernel(const float* __restrict__ w,
                                                  const float* __restrict__ bias,
                                                  const float* __restrict__ we) {
    SMEM_DECL();
    int tid = threadIdx.x, lane = tid & 31, wid = tid >> 5;
    int wm = (wid & 1) * 64, wn = (wid >> 1) * 32;
    int a0 = blockIdx.x * 128, m0 = blockIdx.y * 128;
    int b = m0 >> 10, l0 = m0 & 1023;
    ACC_INIT();
    float2 sa[4], sb[4];
    const int NC = DW / 16;

    auto prefetch = [&](int c) {
        int k0 = c * 16;
#pragma unroll
        for (int s = 0; s < 4; ++s) {
            int p = s * 256 + tid;
            int row = p >> 3, kp = p & 7;
            size_t hb = ((size_t)b * HALF + k0 + 2 * kp) * Lr + l0 + row;
            sa[s].x = g_h[hb];
            sa[s].y = g_h[hb + Lr];
            sb[s] = *(const float2*)&w[(size_t)(a0 + row) * DW + k0 + 2 * kp];
        }
    };

    prefetch(0);
    COMMIT(0)
    __syncthreads();
    for (int c = 0; c < NC; ++c) {
        if (c + 1 < NC) prefetch(c + 1);
        mma_chunk(Ah[c & 1], Al[c & 1], Bh[c & 1], Bl[c & 1], wm, wn, lane, acc);
        if (c + 1 < NC) { int nb = (c + 1) & 1; COMMIT(nb) }
        __syncthreads();
    }

    int r = lane >> 2;
#pragma unroll
    for (int i = 0; i < 4; ++i) {
        int m = m0 + wm + i * 16 + r;
#pragma unroll
        for (int j = 0; j < 4; ++j) {
            int a = a0 + wn + j * 8 + (lane & 3) * 2;
            float2 bb = *(const float2*)&bias[a];
            float2 w0 = *(const float2*)&we[(size_t)m * DW + a];
            float2 w1 = *(const float2*)&we[(size_t)(m + 8) * DW + a];
            *(float2*)&g_q[(size_t)m * DW + a] =
                make_float2(acc[i][j][0] + bb.x + w0.x, acc[i][j][1] + bb.y + w0.y);
            *(float2*)&g_q[(size_t)(m + 8) * DW + a] =
                make_float2(acc[i][j][2] + bb.x + w1.x, acc[i][j][3] + bb.y + w1.y);
        }
    }
}

// ================= score = q @ feat =================
__global__ void __launch_bounds__(256) score_kernel(const float* __restrict__ feat) {
    SMEM_DECL();
    int tid = threadIdx.x, lane = tid & 31, wid = tid >> 5;
    int wm = (wid & 1) * 64, wn = (wid >> 1) * 32;
    int p0 = blockIdx.x * 128, m0 = blockIdx.y * 128;
    int b = m0 >> 10;
    ACC_INIT();
    float2 sa[4], sb[4];
    const int NC = DW / 16;

    auto prefetch = [&](int c) {
        int k0 = c * 16;
#pragma unroll
        for (int s = 0; s < 4; ++s) {
            int p = s * 256 + tid;
            int row = p >> 3, kp = p & 7;
            sa[s] = *(const float2*)&g_q[(size_t)(m0 + row) * DW + k0 + 2 * kp];
            int pp = p0 + row;
            if (pp < HW) {
                size_t fb = ((size_t)b * DW + k0 + 2 * kp) * HW + pp;
                sb[s].x = feat[fb];
                sb[s].y = feat[fb + HW];
            } else {
                sb[s] = make_float2(0.f, 0.f);
            }
        }
    };

    prefetch(0);
    COMMIT(0)
    __syncthreads();
    for (int c = 0; c < NC; ++c) {
        if (c + 1 < NC) prefetch(c + 1);
        mma_chunk(Ah[c & 1], Al[c & 1], Bh[c & 1], Bl[c & 1], wm, wn, lane, acc);
        if (c + 1 < NC) { int nb = (c + 1) & 1; COMMIT(nb) }
        __syncthreads();
    }

    int r = lane >> 2;
#pragma unroll
    for (int i = 0; i < 4; ++i) {
        int m = m0 + wm + i * 16 + r;
#pragma unroll
        for (int j = 0; j < 4; ++j) {
            int p = p0 + wn + j * 8 + (lane & 3) * 2;
            if (p < HW) {
                *(float2*)&g_score[(size_t)m * HW + p] =
                    make_float2(acc[i][j][0], acc[i][j][1]);
                *(float2*)&g_score[(size_t)(m + 8) * HW + p] =
                    make_float2(acc[i][j][2], acc[i][j][3]);
            }
        }
    }
}

// ================= softmax over 196 (one warp per row) =================
__global__ void softmax_kernel(float* __restrict__ attn) {
    int warp = (blockIdx.x * blockDim.x + threadIdx.x) >> 5;
    int lane = threadIdx.x & 31;
    if (warp >= Bn * Lr) return;
    const float* sp = g_score + (size_t)warp * HW;
    float v[7];
    float mx = -1e30f;
#pragma unroll
    for (int i = 0; i < 7; ++i) {
        int p = lane + 32 * i;
        v[i] = (p < HW) ? sp[p] : -1e30f;
        mx = fmaxf(mx, v[i]);
    }
#pragma unroll
    for (int o = 16; o > 0; o >>= 1) mx = fmaxf(mx, __shfl_xor_sync(0xffffffffu, mx, o));
    float sum = 0.f;
#pragma unroll
    for (int i = 0; i < 7; ++i) {
        int p = lane + 32 * i;
        v[i] = (p < HW) ? expf(v[i] - mx) : 0.f;
        sum += v[i];
    }
#pragma unroll
    for (int o = 16; o > 0; o >>= 1) sum += __shfl_xor_sync(0xffffffffu, sum, o);
    float inv = 1.f / sum;
#pragma unroll
    for (int i = 0; i < 7; ++i) {
        int p = lane + 32 * i;
        if (p < HW) attn[(size_t)warp * HW + p] = v[i] * inv;
    }
}

// ================= ctx = attn @ feat^T =================
__global__ void __launch_bounds__(256) ctx_kernel(const float* __restrict__ attn,
                                                  const float* __restrict__ feat) {
    SMEM_DECL();
    int tid = threadIdx.x, lane = tid & 31, wid = tid >> 5;
    int wm = (wid & 1) * 64, wn = (wid >> 1) * 32;
    int a0 = blockIdx.x * 128, m0 = blockIdx.y * 128;
    int b = m0 >> 10;
    ACC_INIT();
    float2 sa[4], sb[4];
    const int NC = 13;  // ceil(196/16)

    auto prefetch = [&](int c) {
        int k0 = c * 16;
#pragma unroll
        for (int s = 0; s < 4; ++s) {
            int p = s * 256 + tid;
            int row = p >> 3, kp = p & 7;
            int kk = k0 + 2 * kp;
            if (kk < HW) {  // pairs fully valid or fully invalid (HW even)
                sa[s] = *(const float2*)&attn[(size_t)(m0 + row) * HW + kk];
                sb[s] = *(const float2*)&feat[((size_t)b * DW + a0 + row) * HW + kk];
            } else {
                sa[s] = make_float2(0.f, 0.f);
                sb[s] = make_float2(0.f, 0.f);
            }
        }
    };

    prefetch(0);
    COMMIT(0)
    __syncthreads();
    for (int c = 0; c < NC; ++c) {
        if (c + 1 < NC) prefetch(c + 1);
        mma_chunk(Ah[c & 1], Al[c & 1], Bh[c & 1], Bl[c & 1], wm, wn, lane, acc);
        if (c + 1 < NC) { int nb = (c + 1) & 1; COMMIT(nb) }
        __syncthreads();
    }

    int r = lane >> 2;
#pragma unroll
    for (int i = 0; i < 4; ++i) {
        int m = m0 + wm + i * 16 + r;
#pragma unroll
        for (int j = 0; j < 4; ++j) {
            int a = a0 + wn + j * 8 + (lane & 3) * 2;
            *(float2*)&g_ctx[(size_t)m * DW + a] = make_float2(acc[i][j][0], acc[i][j][1]);
            *(float2*)&g_ctx[(size_t)(m + 8) * DW + a] = make_float2(acc[i][j][2], acc[i][j][3]);
        }
    }
}

// ================= fc2 + residuals, transposed output =================
__global__ void __launch_bounds__(256) fc2_kernel(const float* __restrict__ w,
                                                  const float* __restrict__ bias,
                                                  const float* __restrict__ x,
                                                  float* __restrict__ out) {
    SMEM_DECL();
    int tid = threadIdx.x, lane = tid & 31, wid = tid >> 5;
    int wm = (wid & 1) * 64, wn = (wid >> 1) * 32;
    int l0 = blockIdx.x * 128, c0 = blockIdx.y * 128, b = blockIdx.z;
    ACC_INIT();
    float2 sa[4], sb[4];
    const int NC = DW / 16;

    auto prefetch = [&](int c) {
        int k0 = c * 16;
#pragma unroll
        for (int s = 0; s < 4; ++s) {
            int p = s * 256 + tid;
            int row = p >> 3, kp = p & 7;
            sa[s] = *(const float2*)&w[(size_t)(c0 + row) * DW + k0 + 2 * kp];
            sb[s] = *(const float2*)&g_ctx[((size_t)b * Lr + l0 + row) * DW + k0 + 2 * kp];
        }
    };

    prefetch(0);
    COMMIT(0)
    __syncthreads();
    for (int c = 0; c < NC; ++c) {
        if (c + 1 < NC) prefetch(c + 1);
        mma_chunk(Ah[c & 1], Al[c & 1], Bh[c & 1], Bl[c & 1], wm, wn, lane, acc);
        if (c + 1 < NC) { int nb = (c + 1) & 1; COMMIT(nb) }
        __syncthreads();
    }

    int r = lane >> 2;
#pragma unroll
    for (int i = 0; i < 4; ++i) {
        int cc = c0 + wm + i * 16 + r;
        float b0 = bias[cc], b1 = bias[cc + 8];
#pragma unroll
        for (int j = 0; j < 4; ++j) {
            int l = l0 + wn + j * 8 + (lane & 3) * 2;
            size_t o0 = ((size_t)b * HALF + cc) * Lr + l;
            size_t o1 = ((size_t)b * HALF + cc + 8) * Lr + l;
            float2 h0 = *(const float2*)&g_h[o0];
            float2 x0 = *(const float2*)&x[o0];
            float2 h1 = *(const float2*)&g_h[o1];
            float2 x1 = *(const float2*)&x[o1];
            *(float2*)&out[o0] = make_float2(acc[i][j][0] + b0 + h0.x + x0.x,
                                             acc[i][j][1] + b0 + h0.y + x0.y);
            *(float2*)&out[o1] = make_float2(acc[i][j][2] + b1 + h1.x + x1.x,
                                             acc[i][j][3] + b1 + h1.y + x1.y);
        }
    }
}

// ================= launch =================
extern "C" void kernel_launch(void* const* d_in, const int* in_sizes, int n_in,
                              void* d_out, int out_size) {
    const float* x      = (const float*)d_in[0];
    const float* we     = (const float*)d_in[1];
    const float* img    = (const float*)d_in[2];
    // d_in[3] prev_attn unused by reference
    const float* conv_v = (const float*)d_in[4];
    const float* conv_g = (const float*)d_in[5];
    const float* conv_b = (const float*)d_in[6];
    const float* fc1_w  = (const float*)d_in[7];
    const float* fc1_b  = (const float*)d_in[8];
    const float* fc2_w  = (const float*)d_in[9];
    const float* fc2_b  = (const float*)d_in[10];

    float* out = (float*)d_out;
    const size_t SZ_OUT = (size_t)Bn * HALF * Lr;  // 8388608
    const size_t SZ_WE  = (size_t)Bn * Lr * DW;    // 8388608
    const size_t SZ_IMG = (size_t)Bn * DW * HW;    // 1605632
    float* out_we   = out + SZ_OUT;
    float* out_img  = out_we + SZ_WE;
    float* out_attn = out_img + SZ_IMG;

    wnorm_kernel<<<COUT, 256>>>(conv_v, conv_g);
    conv_kernel<<<dim3(Lr / 128, COUT / 128, Bn), 256>>>(x, conv_b);
    glu_kernel<<<(Bn * HALF * Lr) / 512, 256>>>();
    fc1_kernel<<<dim3(DW / 128, (Bn * Lr) / 128), 256>>>(fc1_w, fc1_b, we);
    score_kernel<<<dim3(2, (Bn * Lr) / 128), 256>>>(img);
    softmax_kernel<<<(Bn * Lr) / 8, 256>>>(out_attn);
    ctx_kernel<<<dim3(DW / 128, (Bn * Lr) / 128), 256>>>(out_attn, img);
    fc2_kernel<<<dim3(Lr / 128, HALF / 128, Bn), 256>>>(fc2_w, fc2_b, x, out);

    cudaMemcpyAsync(out_we, we, SZ_WE * sizeof(float), cudaMemcpyDeviceToDevice, 0);
    cudaMemcpyAsync(out_img, img, SZ_IMG * sizeof(float), cudaMemcpyDeviceToDevice, 0);
}